// round 1
// baseline (speedup 1.0000x reference)
#include <cuda_runtime.h>
#include <cuda_bf16.h>
#include <cstddef>

// ---------------------------------------------------------------------------
// CrossAttention:
//   Q = x1 @ Wq^T ; K = x2 @ Wk^T ; V = x2 @ Wv^T          [16384, 1024] each
//   per token t (B*M = 16384):
//     S[c][d]   = (1/8) * sum_h K[t][h][c] * Q[t][h][d]     (h=16, c,d=64)
//     S         = softmax over d (rows)
//     AO[t][h][d] = sum_v V[t][h][v] * S[v][d]
//   out = AO @ Wo^T + bo                                     [16384, 1024]
// ---------------------------------------------------------------------------

#define TOKENS  16384          // B*M = 8*2048
#define FEAT    1024           // hk = hv = seq_len1 = seq_len2
#define NH      16
#define HD      64

// Scratch (allocation-free rule: static __device__ arrays)
__device__ float g_Q [(size_t)TOKENS * FEAT];
__device__ float g_K [(size_t)TOKENS * FEAT];
__device__ float g_V [(size_t)TOKENS * FEAT];
__device__ float g_AO[(size_t)TOKENS * FEAT];

// ---------------------------------------------------------------------------
// SGEMM: C[M][N] = A[M][K] * W[N][K]^T (+ bias[N] if bias != nullptr)
// BM=BN=128, BK=16, 256 threads, 8x8 per-thread tile.
// ---------------------------------------------------------------------------
#define BM 128
#define BN 128
#define BK 16
#define TM 8
#define TN 8

__global__ __launch_bounds__(256) void sgemm_nt(
    const float* __restrict__ A, const float* __restrict__ W,
    const float* __restrict__ bias, float* __restrict__ C,
    int M, int N, int K)
{
    __shared__ float As[BK][BM];
    __shared__ float Ws[BK][BN];

    const int tid = threadIdx.x;
    const int m0  = blockIdx.y * BM;
    const int n0  = blockIdx.x * BN;
    const int tr  = tid >> 4;    // 0..15
    const int tc  = tid & 15;    // 0..15

    float acc[TM][TN];
    #pragma unroll
    for (int i = 0; i < TM; i++)
        #pragma unroll
        for (int j = 0; j < TN; j++)
            acc[i][j] = 0.0f;

    for (int k0 = 0; k0 < K; k0 += BK) {
        // 512 float4 per operand tile; each thread moves 2 of each.
        #pragma unroll
        for (int l = 0; l < 2; l++) {
            int i   = tid + l * 256;
            int row = i >> 2;            // 0..127
            int c4  = (i & 3) << 2;      // 0,4,8,12
            float4 a = *reinterpret_cast<const float4*>(
                A + (size_t)(m0 + row) * K + k0 + c4);
            As[c4 + 0][row] = a.x;  As[c4 + 1][row] = a.y;
            As[c4 + 2][row] = a.z;  As[c4 + 3][row] = a.w;
            float4 w = *reinterpret_cast<const float4*>(
                W + (size_t)(n0 + row) * K + k0 + c4);
            Ws[c4 + 0][row] = w.x;  Ws[c4 + 1][row] = w.y;
            Ws[c4 + 2][row] = w.z;  Ws[c4 + 3][row] = w.w;
        }
        __syncthreads();

        #pragma unroll
        for (int k = 0; k < BK; k++) {
            float a[TM], w[TN];
            // vectorized smem reads (16B aligned: BM multiple of 4)
            *reinterpret_cast<float4*>(&a[0]) =
                *reinterpret_cast<const float4*>(&As[k][tr * TM + 0]);
            *reinterpret_cast<float4*>(&a[4]) =
                *reinterpret_cast<const float4*>(&As[k][tr * TM + 4]);
            *reinterpret_cast<float4*>(&w[0]) =
                *reinterpret_cast<const float4*>(&Ws[k][tc * TN + 0]);
            *reinterpret_cast<float4*>(&w[4]) =
                *reinterpret_cast<const float4*>(&Ws[k][tc * TN + 4]);
            #pragma unroll
            for (int i = 0; i < TM; i++)
                #pragma unroll
                for (int j = 0; j < TN; j++)
                    acc[i][j] = fmaf(a[i], w[j], acc[i][j]);
        }
        __syncthreads();
    }

    #pragma unroll
    for (int i = 0; i < TM; i++) {
        const int m = m0 + tr * TM + i;
        float* crow = C + (size_t)m * N + n0 + tc * TN;
        #pragma unroll
        for (int j = 0; j < TN; j += 4) {
            float4 v;
            v.x = acc[i][j + 0];
            v.y = acc[i][j + 1];
            v.z = acc[i][j + 2];
            v.w = acc[i][j + 3];
            if (bias) {
                const float* b = bias + n0 + tc * TN + j;
                v.x += b[0]; v.y += b[1]; v.z += b[2]; v.w += b[3];
            }
            *reinterpret_cast<float4*>(crow + j) = v;
        }
    }
}

// ---------------------------------------------------------------------------
// Per-token attention: one block per token, 256 threads.
// ---------------------------------------------------------------------------
__global__ __launch_bounds__(256) void attn_kernel(
    const float* __restrict__ Q, const float* __restrict__ K2,
    const float* __restrict__ V2, float* __restrict__ O)
{
    const int t   = blockIdx.x;
    const int tid = threadIdx.x;

    __shared__ float q[NH][HD];
    __shared__ float k[NH][HD];
    __shared__ float v[NH][HD];
    __shared__ float S[HD][HD + 1];   // +1 pad: conflict-free column access

    const size_t base = (size_t)t * FEAT;
    for (int i = tid; i < FEAT; i += 256) {
        q[i >> 6][i & 63] = Q [base + i];
        k[i >> 6][i & 63] = K2[base + i];
        v[i >> 6][i & 63] = V2[base + i];
    }
    __syncthreads();

    // S[c][d] = (1/8) * sum_h k[h][c] * q[h][d]
    for (int i = tid; i < HD * HD; i += 256) {
        const int c = i >> 6, d = i & 63;
        float s = 0.0f;
        #pragma unroll
        for (int h = 0; h < NH; h++)
            s = fmaf(k[h][c], q[h][d], s);
        S[c][d] = s * 0.125f;
    }
    __syncthreads();

    // softmax over d for each row c (64 threads, one row each)
    if (tid < HD) {
        float mx = -1e30f;
        #pragma unroll 8
        for (int d = 0; d < HD; d++) mx = fmaxf(mx, S[tid][d]);
        float sum = 0.0f;
        #pragma unroll 8
        for (int d = 0; d < HD; d++) {
            float e = __expf(S[tid][d] - mx);
            S[tid][d] = e;
            sum += e;
        }
        const float inv = 1.0f / sum;
        #pragma unroll 8
        for (int d = 0; d < HD; d++) S[tid][d] *= inv;
    }
    __syncthreads();

    // O[h][d] = sum_v v[h][v] * S[v][d]
    for (int i = tid; i < FEAT; i += 256) {
        const int h = i >> 6, d = i & 63;
        float s = 0.0f;
        #pragma unroll
        for (int vv = 0; vv < HD; vv++)
            s = fmaf(v[h][vv], S[vv][d], s);
        O[base + i] = s;
    }
}

// ---------------------------------------------------------------------------
// Launcher
// ---------------------------------------------------------------------------
extern "C" void kernel_launch(void* const* d_in, const int* in_sizes, int n_in,
                              void* d_out, int out_size)
{
    const float* x1 = (const float*)d_in[0];
    const float* x2 = (const float*)d_in[1];
    const float* Wq = (const float*)d_in[2];
    const float* Wk = (const float*)d_in[3];
    const float* Wv = (const float*)d_in[4];
    const float* Wo = (const float*)d_in[5];
    const float* bo = (const float*)d_in[6];
    float*       out = (float*)d_out;

    float *Q, *K, *V, *AO;
    cudaGetSymbolAddress((void**)&Q,  g_Q);
    cudaGetSymbolAddress((void**)&K,  g_K);
    cudaGetSymbolAddress((void**)&V,  g_V);
    cudaGetSymbolAddress((void**)&AO, g_AO);

    const dim3 gg(FEAT / BN, TOKENS / BM);   // (8, 128)
    const dim3 gb(256);

    sgemm_nt<<<gg, gb>>>(x1, Wq, nullptr, Q, TOKENS, FEAT, FEAT);
    sgemm_nt<<<gg, gb>>>(x2, Wk, nullptr, K, TOKENS, FEAT, FEAT);
    sgemm_nt<<<gg, gb>>>(x2, Wv, nullptr, V, TOKENS, FEAT, FEAT);

    attn_kernel<<<TOKENS, 256>>>(Q, K, V, AO);

    sgemm_nt<<<gg, gb>>>(AO, Wo, bo, out, TOKENS, FEAT, FEAT);
}

// round 2
// speedup vs baseline: 2.3868x; 2.3868x over previous
#include <cuda_runtime.h>
#include <cuda_bf16.h>
#include <cstdint>
#include <cstddef>

// ---------------------------------------------------------------------------
// CrossAttention:
//   Q = x1 @ Wq^T ; K = x2 @ Wk^T ; V = x2 @ Wv^T          [16384, 1024] each
//   per token t: S = softmax_rows((1/8) K_t^T Q_t), O_t = V_t S
//   out = AO @ Wo^T + bo                                    [16384, 1024]
// GEMMs on tensor cores via mma.sync tf32; attention in fp32.
// ---------------------------------------------------------------------------

#define TOKENS  16384
#define FEAT    1024
#define NH      16
#define HD      64

__device__ float g_Q [(size_t)TOKENS * FEAT];
__device__ float g_K [(size_t)TOKENS * FEAT];
__device__ float g_V [(size_t)TOKENS * FEAT];
__device__ float g_AO[(size_t)TOKENS * FEAT];

// ---------------------------------------------------------------------------
// tf32 tensor-core GEMM: C[M][N] = A[M][K] * W[N][K]^T (+bias)
// BM=BN=128, BK=32, 256 threads (8 warps as 2x4), warp tile 64x32,
// m16n8k8 fragments. Smem row stride 36 words:
//   - frag loads: bank = (36*r + k) % 32 = (4r + k) % 32, r in 0..7 x k in 0..3
//     all distinct -> conflict-free
//   - uint4 tile stores: 8 lanes cover one 128B row segment -> conflict-free
// ---------------------------------------------------------------------------
#define GBM 128
#define GBN 128
#define GBK 32
#define LDSW 36

__device__ __forceinline__ uint32_t f2tf32(float x) {
    uint32_t r;
    asm("cvt.rna.tf32.f32 %0, %1;" : "=r"(r) : "f"(x));
    return r;
}

__device__ __forceinline__ void mma_tf32(float* c, const uint32_t* a, const uint32_t* b) {
    asm volatile(
        "mma.sync.aligned.m16n8k8.row.col.f32.tf32.tf32.f32 "
        "{%0,%1,%2,%3},{%4,%5,%6,%7},{%8,%9},{%0,%1,%2,%3};"
        : "+f"(c[0]), "+f"(c[1]), "+f"(c[2]), "+f"(c[3])
        : "r"(a[0]), "r"(a[1]), "r"(a[2]), "r"(a[3]), "r"(b[0]), "r"(b[1]));
}

__global__ __launch_bounds__(256, 2) void gemm_tf32(
    const float* __restrict__ A, const float* __restrict__ W,
    const float* __restrict__ bias, float* __restrict__ C,
    int M, int N, int K)
{
    __shared__ uint32_t As[GBM][LDSW];
    __shared__ uint32_t Ws[GBN][LDSW];

    const int tid  = threadIdx.x;
    const int wid  = tid >> 5;
    const int lane = tid & 31;
    const int gid  = lane >> 2;     // 0..7
    const int tid4 = lane & 3;      // 0..3
    const int m0 = blockIdx.y * GBM;
    const int n0 = blockIdx.x * GBN;
    const int wm = (wid & 1) * 64;  // warp m-origin within tile
    const int wn = (wid >> 1) * 32; // warp n-origin within tile

    float acc[4][4][4];
    #pragma unroll
    for (int i = 0; i < 4; i++)
        #pragma unroll
        for (int j = 0; j < 4; j++)
            #pragma unroll
            for (int l = 0; l < 4; l++)
                acc[i][j][l] = 0.0f;

    for (int k0 = 0; k0 < K; k0 += GBK) {
        // load 128x32 tiles of A and W, convert fp32->tf32, uint4 stores
        #pragma unroll
        for (int l = 0; l < 4; l++) {
            const int i   = tid + l * 256;
            const int row = i >> 3;          // 0..127
            const int c4  = (i & 7) << 2;    // 0,4,...,28
            float4 a = *reinterpret_cast<const float4*>(
                A + (size_t)(m0 + row) * K + k0 + c4);
            uint4 ap = make_uint4(f2tf32(a.x), f2tf32(a.y), f2tf32(a.z), f2tf32(a.w));
            *reinterpret_cast<uint4*>(&As[row][c4]) = ap;
            float4 w = *reinterpret_cast<const float4*>(
                W + (size_t)(n0 + row) * K + k0 + c4);
            uint4 wp = make_uint4(f2tf32(w.x), f2tf32(w.y), f2tf32(w.z), f2tf32(w.w));
            *reinterpret_cast<uint4*>(&Ws[row][c4]) = wp;
        }
        __syncthreads();

        #pragma unroll
        for (int kk = 0; kk < GBK; kk += 8) {
            uint32_t af[4][4], bf[4][2];
            #pragma unroll
            for (int mt = 0; mt < 4; mt++) {
                const int r = wm + mt * 16 + gid;
                af[mt][0] = As[r    ][kk + tid4];
                af[mt][1] = As[r + 8][kk + tid4];
                af[mt][2] = As[r    ][kk + tid4 + 4];
                af[mt][3] = As[r + 8][kk + tid4 + 4];
            }
            #pragma unroll
            for (int nt = 0; nt < 4; nt++) {
                const int cB = wn + nt * 8 + gid;
                bf[nt][0] = Ws[cB][kk + tid4];
                bf[nt][1] = Ws[cB][kk + tid4 + 4];
            }
            #pragma unroll
            for (int mt = 0; mt < 4; mt++)
                #pragma unroll
                for (int nt = 0; nt < 4; nt++)
                    mma_tf32(acc[mt][nt], af[mt], bf[nt]);
        }
        __syncthreads();
    }

    // epilogue: c0,c1 at (row, col..col+1); c2,c3 at (row+8, ...)
    #pragma unroll
    for (int mt = 0; mt < 4; mt++) {
        const int row0 = m0 + wm + mt * 16 + gid;
        #pragma unroll
        for (int nt = 0; nt < 4; nt++) {
            const int col = n0 + wn + nt * 8 + 2 * tid4;
            float b0 = 0.0f, b1 = 0.0f;
            if (bias) { b0 = bias[col]; b1 = bias[col + 1]; }
            float2 v0 = make_float2(acc[mt][nt][0] + b0, acc[mt][nt][1] + b1);
            float2 v1 = make_float2(acc[mt][nt][2] + b0, acc[mt][nt][3] + b1);
            *reinterpret_cast<float2*>(C + (size_t)row0 * N + col)       = v0;
            *reinterpret_cast<float2*>(C + (size_t)(row0 + 8) * N + col) = v1;
        }
    }
}

// ---------------------------------------------------------------------------
// Per-token attention: one block per token, 256 threads.
// Thread (c = tid/4) owns 16 interleaved columns d = (tid&3) + 4j
// -> conflict-free S/q reads, ~1.06 smem loads per FMA.
// ---------------------------------------------------------------------------
__global__ __launch_bounds__(256) void attn_kernel(
    const float* __restrict__ Q, const float* __restrict__ K2,
    const float* __restrict__ V2, float* __restrict__ O)
{
    const int t   = blockIdx.x;
    const int tid = threadIdx.x;

    __shared__ float q[NH][HD];
    __shared__ float k[NH][HD];
    __shared__ float v[NH][HD];
    __shared__ float S[HD][HD + 1];

    const size_t base = (size_t)t * FEAT;
    // one float4 per thread per array (1024 floats / 256 threads)
    reinterpret_cast<float4*>(&q[0][0])[tid] = reinterpret_cast<const float4*>(Q  + base)[tid];
    reinterpret_cast<float4*>(&k[0][0])[tid] = reinterpret_cast<const float4*>(K2 + base)[tid];
    reinterpret_cast<float4*>(&v[0][0])[tid] = reinterpret_cast<const float4*>(V2 + base)[tid];
    __syncthreads();

    const int c  = tid >> 2;        // row 0..63
    const int dl = tid & 3;         // column lane 0..3 (d = dl + 4j)

    // S[c][d] = (1/8) * sum_h k[h][c] * q[h][d]
    {
        float acc[16];
        #pragma unroll
        for (int j = 0; j < 16; j++) acc[j] = 0.0f;
        #pragma unroll
        for (int h = 0; h < NH; h++) {
            const float kv = k[h][c];
            #pragma unroll
            for (int j = 0; j < 16; j++)
                acc[j] = fmaf(kv, q[h][dl + 4 * j], acc[j]);
        }
        #pragma unroll
        for (int j = 0; j < 16; j++)
            S[c][dl + 4 * j] = acc[j] * 0.125f;
    }
    __syncthreads();

    // softmax over d for row c; 4 threads/row, quad reduction via shfl
    {
        float mx = -1e30f;
        #pragma unroll
        for (int j = 0; j < 16; j++) mx = fmaxf(mx, S[c][dl + 4 * j]);
        mx = fmaxf(mx, __shfl_xor_sync(0xFFFFFFFFu, mx, 1));
        mx = fmaxf(mx, __shfl_xor_sync(0xFFFFFFFFu, mx, 2));
        float sum = 0.0f;
        #pragma unroll
        for (int j = 0; j < 16; j++) {
            float e = __expf(S[c][dl + 4 * j] - mx);
            S[c][dl + 4 * j] = e;
            sum += e;
        }
        sum += __shfl_xor_sync(0xFFFFFFFFu, sum, 1);
        sum += __shfl_xor_sync(0xFFFFFFFFu, sum, 2);
        const float inv = 1.0f / sum;
        #pragma unroll
        for (int j = 0; j < 16; j++) S[c][dl + 4 * j] *= inv;
    }
    __syncthreads();

    // O[h][d] = sum_v v[h][vv] * S[vv][d]  (h = c mapping reused: h = tid>>2 & 15? no:
    // 256 threads / 4 lanes = 64 rows, but h only 0..15 -> 4 tokens of parallel h? 
    // Here: thread row = tid>>2 in 0..63; h = row & 15, and rows 16..63 duplicate h
    // would collide. Instead: h = tid >> 4 (0..15), lane16 = tid & 15 gives d-slot.)
    {
        const int h   = tid >> 4;       // 0..15
        const int dl2 = tid & 15;       // d = dl2 + 16j? -> 4 outputs per thread
        float o[4];
        #pragma unroll
        for (int j = 0; j < 4; j++) o[j] = 0.0f;
        #pragma unroll
        for (int vv = 0; vv < HD; vv++) {
            const float vl = v[h][vv];
            #pragma unroll
            for (int j = 0; j < 4; j++)
                o[j] = fmaf(vl, S[vv][dl2 + 16 * j], o[j]);
        }
        #pragma unroll
        for (int j = 0; j < 4; j++)
            O[base + h * HD + dl2 + 16 * j] = o[j];
    }
}

// ---------------------------------------------------------------------------
// Launcher
// ---------------------------------------------------------------------------
extern "C" void kernel_launch(void* const* d_in, const int* in_sizes, int n_in,
                              void* d_out, int out_size)
{
    const float* x1 = (const float*)d_in[0];
    const float* x2 = (const float*)d_in[1];
    const float* Wq = (const float*)d_in[2];
    const float* Wk = (const float*)d_in[3];
    const float* Wv = (const float*)d_in[4];
    const float* Wo = (const float*)d_in[5];
    const float* bo = (const float*)d_in[6];
    float*       out = (float*)d_out;

    float *Q, *K, *V, *AO;
    cudaGetSymbolAddress((void**)&Q,  g_Q);
    cudaGetSymbolAddress((void**)&K,  g_K);
    cudaGetSymbolAddress((void**)&V,  g_V);
    cudaGetSymbolAddress((void**)&AO, g_AO);

    const dim3 gg(FEAT / GBN, TOKENS / GBM);   // (8, 128)
    const dim3 gb(256);

    gemm_tf32<<<gg, gb>>>(x1, Wq, nullptr, Q, TOKENS, FEAT, FEAT);
    gemm_tf32<<<gg, gb>>>(x2, Wk, nullptr, K, TOKENS, FEAT, FEAT);
    gemm_tf32<<<gg, gb>>>(x2, Wv, nullptr, V, TOKENS, FEAT, FEAT);

    attn_kernel<<<TOKENS, 256>>>(Q, K, V, AO);

    gemm_tf32<<<gg, gb>>>(AO, Wo, bo, out, TOKENS, FEAT, FEAT);
}

// round 6
// speedup vs baseline: 3.5560x; 1.4899x over previous
#include <cuda_runtime.h>
#include <cuda_fp16.h>
#include <cstdint>
#include <cstddef>

// ---------------------------------------------------------------------------
// CrossAttention on sm_100 (base ISA — no tcgen05):
//   fp32->fp16 convert; 4 GEMMs via mma.sync.m16n8k16.f16 (fp32 accum),
//   cp.async double-buffered smem; per-token attention fp32 SIMT.
// ---------------------------------------------------------------------------

#define TOKENS  16384
#define FEAT    1024
#define NH      16
#define HD      64

__device__ __half g_hx1[(size_t)TOKENS * FEAT];
__device__ __half g_hx2[(size_t)TOKENS * FEAT];
__device__ __half g_hWq[(size_t)FEAT * FEAT];
__device__ __half g_hWk[(size_t)FEAT * FEAT];
__device__ __half g_hWv[(size_t)FEAT * FEAT];
__device__ __half g_hWo[(size_t)FEAT * FEAT];
__device__ float  g_Q  [(size_t)TOKENS * FEAT];
__device__ float  g_K  [(size_t)TOKENS * FEAT];
__device__ float  g_V  [(size_t)TOKENS * FEAT];
__device__ __half g_AOh[(size_t)TOKENS * FEAT];

// ---------------------------------------------------------------------------
// helpers
// ---------------------------------------------------------------------------
__device__ __forceinline__ uint32_t smem_u32(const void* p) {
    uint32_t a;
    asm("{ .reg .u64 t; cvta.to.shared.u64 t, %1; cvt.u32.u64 %0, t; }"
        : "=r"(a) : "l"(p));
    return a;
}

#define CP_ASYNC16(dst, src) \
    asm volatile("cp.async.cg.shared.global [%0], [%1], 16;" :: "r"(dst), "l"(src))
#define CP_COMMIT() asm volatile("cp.async.commit_group;" ::: "memory")
#define CP_WAIT(n)  asm volatile("cp.async.wait_group %0;" :: "n"(n) : "memory")

__device__ __forceinline__ void mma_f16(float* c, const uint32_t* a, const uint32_t* b) {
    asm volatile(
        "mma.sync.aligned.m16n8k16.row.col.f32.f16.f16.f32 "
        "{%0,%1,%2,%3},{%4,%5,%6,%7},{%8,%9},{%0,%1,%2,%3};"
        : "+f"(c[0]), "+f"(c[1]), "+f"(c[2]), "+f"(c[3])
        : "r"(a[0]), "r"(a[1]), "r"(a[2]), "r"(a[3]), "r"(b[0]), "r"(b[1]));
}

// ---------------------------------------------------------------------------
// fp32 -> fp16 convert
// ---------------------------------------------------------------------------
__global__ __launch_bounds__(256) void f2h_kernel(
    const float* __restrict__ src, __half* __restrict__ dst, int n)
{
    const int stride = gridDim.x * blockDim.x * 4;
    for (int i = (blockIdx.x * blockDim.x + threadIdx.x) * 4; i < n; i += stride) {
        float4 v = *reinterpret_cast<const float4*>(src + i);
        *reinterpret_cast<__half2*>(dst + i)     = __float22half2_rn(make_float2(v.x, v.y));
        *reinterpret_cast<__half2*>(dst + i + 2) = __float22half2_rn(make_float2(v.z, v.w));
    }
}

// ---------------------------------------------------------------------------
// fp16 tensor-core GEMM: C[M][N](f32) = A[M][K](f16) * W[N][K](f16)^T (+bias)
// BM=BN=128, BK=32, 256 threads (8 warps as 2x4), warp tile 64x32,
// m16n8k16 fragments, cp.async 2-stage double buffer.
// Smem rows: 16 half2-words (BK=32 halves) padded to stride 20 words (80B,
// 16B-aligned). Fragment loads: bank = (20*g + t4) % 32, g=0..7 x t4=0..3
// all distinct -> conflict-free.
// ---------------------------------------------------------------------------
#define GBK   32
#define LDSW  20
#define NCH   (FEAT / GBK)    // 32 chunks

__global__ __launch_bounds__(256, 2) void gemm_f16(
    const __half* __restrict__ A, const __half* __restrict__ W,
    const float* __restrict__ bias, float* __restrict__ C,
    int M, int N, int K)
{
    __shared__ uint32_t As[2][128][LDSW];
    __shared__ uint32_t Ws[2][128][LDSW];

    const int tid  = threadIdx.x;
    const int wid  = tid >> 5;
    const int lane = tid & 31;
    const int gid  = lane >> 2;     // 0..7
    const int t4   = lane & 3;      // 0..3
    const int m0 = blockIdx.y * 128;
    const int n0 = blockIdx.x * 128;
    const int wm = (wid & 1) * 64;
    const int wn = (wid >> 1) * 32;

    const uint32_t sA = smem_u32(&As[0][0][0]);
    const uint32_t sW = smem_u32(&Ws[0][0][0]);
    const uint32_t BUFB = 128 * LDSW * 4;   // bytes per buffer

    // per-thread load slots: chunks tid and tid+256 of 512 16B-chunks per tile
    const int r0_  = tid >> 2,          seg0 = tid & 3;
    const int r1_  = (tid + 256) >> 2,  seg1 = (tid + 256) & 3;

    float acc[4][4][4];
    #pragma unroll
    for (int i = 0; i < 4; i++)
        #pragma unroll
        for (int j = 0; j < 4; j++)
            #pragma unroll
            for (int l = 0; l < 4; l++)
                acc[i][j][l] = 0.0f;

    // prefetch chunk 0 into buffer 0
    {
        const int k0 = 0;
        CP_ASYNC16(sA + 0 * BUFB + r0_ * 80 + seg0 * 16,
                   A + (size_t)(m0 + r0_) * K + k0 + seg0 * 8);
        CP_ASYNC16(sA + 0 * BUFB + r1_ * 80 + seg1 * 16,
                   A + (size_t)(m0 + r1_) * K + k0 + seg1 * 8);
        CP_ASYNC16(sW + 0 * BUFB + r0_ * 80 + seg0 * 16,
                   W + (size_t)(n0 + r0_) * K + k0 + seg0 * 8);
        CP_ASYNC16(sW + 0 * BUFB + r1_ * 80 + seg1 * 16,
                   W + (size_t)(n0 + r1_) * K + k0 + seg1 * 8);
        CP_COMMIT();
    }

    const int nch = K / GBK;
    for (int c = 0; c < nch; c++) {
        const int s = c & 1;
        if (c + 1 < nch) {
            const int k0 = (c + 1) * GBK;
            const uint32_t sn = (uint32_t)((c + 1) & 1) * BUFB;
            CP_ASYNC16(sA + sn + r0_ * 80 + seg0 * 16,
                       A + (size_t)(m0 + r0_) * K + k0 + seg0 * 8);
            CP_ASYNC16(sA + sn + r1_ * 80 + seg1 * 16,
                       A + (size_t)(m0 + r1_) * K + k0 + seg1 * 8);
            CP_ASYNC16(sW + sn + r0_ * 80 + seg0 * 16,
                       W + (size_t)(n0 + r0_) * K + k0 + seg0 * 8);
            CP_ASYNC16(sW + sn + r1_ * 80 + seg1 * 16,
                       W + (size_t)(n0 + r1_) * K + k0 + seg1 * 8);
            CP_COMMIT();
            CP_WAIT(1);
        } else {
            CP_WAIT(0);
        }
        __syncthreads();

        #pragma unroll
        for (int ks = 0; ks < 2; ks++) {          // two k16 steps per chunk
            const int kc = ks * 8;                 // half2-word offset
            uint32_t af[4][4], bf[4][2];
            #pragma unroll
            for (int mt = 0; mt < 4; mt++) {
                const int r = wm + mt * 16 + gid;
                af[mt][0] = As[s][r    ][kc + t4];
                af[mt][1] = As[s][r + 8][kc + t4];
                af[mt][2] = As[s][r    ][kc + t4 + 4];
                af[mt][3] = As[s][r + 8][kc + t4 + 4];
            }
            #pragma unroll
            for (int nt = 0; nt < 4; nt++) {
                const int cB = wn + nt * 8 + gid;
                bf[nt][0] = Ws[s][cB][kc + t4];
                bf[nt][1] = Ws[s][cB][kc + t4 + 4];
            }
            #pragma unroll
            for (int mt = 0; mt < 4; mt++)
                #pragma unroll
                for (int nt = 0; nt < 4; nt++)
                    mma_f16(acc[mt][nt], af[mt], bf[nt]);
        }
        __syncthreads();
    }

    // epilogue: c0,c1 -> (row, col..col+1); c2,c3 -> (row+8, ...)
    #pragma unroll
    for (int mt = 0; mt < 4; mt++) {
        const int row0 = m0 + wm + mt * 16 + gid;
        #pragma unroll
        for (int nt = 0; nt < 4; nt++) {
            const int col = n0 + wn + nt * 8 + 2 * t4;
            float b0 = 0.0f, b1 = 0.0f;
            if (bias) { b0 = bias[col]; b1 = bias[col + 1]; }
            *reinterpret_cast<float2*>(C + (size_t)row0 * N + col) =
                make_float2(acc[mt][nt][0] + b0, acc[mt][nt][1] + b1);
            *reinterpret_cast<float2*>(C + (size_t)(row0 + 8) * N + col) =
                make_float2(acc[mt][nt][2] + b0, acc[mt][nt][3] + b1);
        }
    }
}

// ---------------------------------------------------------------------------
// Per-token attention, fp32, vectorized smem access. AO written as fp16.
// ---------------------------------------------------------------------------
__global__ __launch_bounds__(256) void attn_kernel(
    const float* __restrict__ Q, const float* __restrict__ K2,
    const float* __restrict__ V2, __half* __restrict__ O)
{
    const int t   = blockIdx.x;
    const int tid = threadIdx.x;

    __shared__ float q[NH][HD];
    __shared__ float k[NH][HD];
    __shared__ float v[NH][HD];
    __shared__ float S[HD][HD + 4];   // row stride 68 floats, rows 16B-aligned

    const size_t base = (size_t)t * FEAT;
    reinterpret_cast<float4*>(&q[0][0])[tid] = reinterpret_cast<const float4*>(Q  + base)[tid];
    reinterpret_cast<float4*>(&k[0][0])[tid] = reinterpret_cast<const float4*>(K2 + base)[tid];
    reinterpret_cast<float4*>(&v[0][0])[tid] = reinterpret_cast<const float4*>(V2 + base)[tid];
    __syncthreads();

    const int c  = tid >> 2;         // S row 0..63
    const int dl = tid & 3;
    const int d0 = dl * 16;          // 16 contiguous columns per thread

    // phase 1: S[c][d] = (1/8) sum_h k[h][c] * q[h][d]
    {
        float kreg[NH];
        #pragma unroll
        for (int h = 0; h < NH; h++) kreg[h] = k[h][c];

        float acc[16];
        #pragma unroll
        for (int j = 0; j < 16; j++) acc[j] = 0.0f;
        #pragma unroll
        for (int h = 0; h < NH; h++) {
            const float kv = kreg[h];
            #pragma unroll
            for (int j4 = 0; j4 < 4; j4++) {
                float4 qv = *reinterpret_cast<const float4*>(&q[h][d0 + 4 * j4]);
                acc[4 * j4 + 0] = fmaf(kv, qv.x, acc[4 * j4 + 0]);
                acc[4 * j4 + 1] = fmaf(kv, qv.y, acc[4 * j4 + 1]);
                acc[4 * j4 + 2] = fmaf(kv, qv.z, acc[4 * j4 + 2]);
                acc[4 * j4 + 3] = fmaf(kv, qv.w, acc[4 * j4 + 3]);
            }
        }
        #pragma unroll
        for (int j4 = 0; j4 < 4; j4++)
            *reinterpret_cast<float4*>(&S[c][d0 + 4 * j4]) =
                make_float4(acc[4 * j4] * 0.125f, acc[4 * j4 + 1] * 0.125f,
                            acc[4 * j4 + 2] * 0.125f, acc[4 * j4 + 3] * 0.125f);
    }
    __syncthreads();

    // phase 2: row softmax (4 lanes per row, quad shfl reduce)
    {
        float e[16];
        #pragma unroll
        for (int j4 = 0; j4 < 4; j4++) {
            float4 sv = *reinterpret_cast<const float4*>(&S[c][d0 + 4 * j4]);
            e[4 * j4 + 0] = sv.x; e[4 * j4 + 1] = sv.y;
            e[4 * j4 + 2] = sv.z; e[4 * j4 + 3] = sv.w;
        }
        float mx = -1e30f;
        #pragma unroll
        for (int j = 0; j < 16; j++) mx = fmaxf(mx, e[j]);
        mx = fmaxf(mx, __shfl_xor_sync(0xFFFFFFFFu, mx, 1));
        mx = fmaxf(mx, __shfl_xor_sync(0xFFFFFFFFu, mx, 2));
        float sum = 0.0f;
        #pragma unroll
        for (int j = 0; j < 16; j++) { e[j] = __expf(e[j] - mx); sum += e[j]; }
        sum += __shfl_xor_sync(0xFFFFFFFFu, sum, 1);
        sum += __shfl_xor_sync(0xFFFFFFFFu, sum, 2);
        const float inv = 1.0f / sum;
        #pragma unroll
        for (int j4 = 0; j4 < 4; j4++)
            *reinterpret_cast<float4*>(&S[c][d0 + 4 * j4]) =
                make_float4(e[4 * j4] * inv, e[4 * j4 + 1] * inv,
                            e[4 * j4 + 2] * inv, e[4 * j4 + 3] * inv);
    }
    __syncthreads();

    // phase 3: O[h][d] = sum_v v[h][vv] * S[vv][d]; 4 contiguous d per thread
    {
        const int h  = tid >> 4;          // 0..15
        const int e0 = (tid & 15) * 4;    // 0..60
        float o0 = 0.f, o1 = 0.f, o2 = 0.f, o3 = 0.f;
        #pragma unroll
        for (int vv = 0; vv < HD; vv++) {
            const float vl = v[h][vv];
            float4 sv = *reinterpret_cast<const float4*>(&S[vv][e0]);
            o0 = fmaf(vl, sv.x, o0);
            o1 = fmaf(vl, sv.y, o1);
            o2 = fmaf(vl, sv.z, o2);
            o3 = fmaf(vl, sv.w, o3);
        }
        __half* dst = O + base + h * HD + e0;
        *reinterpret_cast<__half2*>(dst)     = __float22half2_rn(make_float2(o0, o1));
        *reinterpret_cast<__half2*>(dst + 2) = __float22half2_rn(make_float2(o2, o3));
    }
}

// ---------------------------------------------------------------------------
// Launcher
// ---------------------------------------------------------------------------
extern "C" void kernel_launch(void* const* d_in, const int* in_sizes, int n_in,
                              void* d_out, int out_size)
{
    const float* x1 = (const float*)d_in[0];
    const float* x2 = (const float*)d_in[1];
    const float* Wq = (const float*)d_in[2];
    const float* Wk = (const float*)d_in[3];
    const float* Wv = (const float*)d_in[4];
    const float* Wo = (const float*)d_in[5];
    const float* bo = (const float*)d_in[6];
    float*       out = (float*)d_out;

    __half *hx1, *hx2, *hWq, *hWk, *hWv, *hWo, *AOh;
    float  *Qf, *Kf, *Vf;
    cudaGetSymbolAddress((void**)&hx1, g_hx1);
    cudaGetSymbolAddress((void**)&hx2, g_hx2);
    cudaGetSymbolAddress((void**)&hWq, g_hWq);
    cudaGetSymbolAddress((void**)&hWk, g_hWk);
    cudaGetSymbolAddress((void**)&hWv, g_hWv);
    cudaGetSymbolAddress((void**)&hWo, g_hWo);
    cudaGetSymbolAddress((void**)&AOh, g_AOh);
    cudaGetSymbolAddress((void**)&Qf,  g_Q);
    cudaGetSymbolAddress((void**)&Kf,  g_K);
    cudaGetSymbolAddress((void**)&Vf,  g_V);

    const int nTok = TOKENS * FEAT;
    const int nW   = FEAT * FEAT;
    f2h_kernel<<<nTok / 1024, 256>>>(x1, hx1, nTok);
    f2h_kernel<<<nTok / 1024, 256>>>(x2, hx2, nTok);
    f2h_kernel<<<nW   / 1024, 256>>>(Wq, hWq, nW);
    f2h_kernel<<<nW   / 1024, 256>>>(Wk, hWk, nW);
    f2h_kernel<<<nW   / 1024, 256>>>(Wv, hWv, nW);
    f2h_kernel<<<nW   / 1024, 256>>>(Wo, hWo, nW);

    const dim3 gg(FEAT / 128, TOKENS / 128);   // (8, 128)
    gemm_f16<<<gg, 256>>>(hx1, hWq, nullptr, Qf, TOKENS, FEAT, FEAT);
    gemm_f16<<<gg, 256>>>(hx2, hWk, nullptr, Kf, TOKENS, FEAT, FEAT);
    gemm_f16<<<gg, 256>>>(hx2, hWv, nullptr, Vf, TOKENS, FEAT, FEAT);

    attn_kernel<<<TOKENS, 256>>>(Qf, Kf, Vf, AOh);

    gemm_f16<<<gg, 256>>>(AOh, hWo, bo, out, TOKENS, FEAT, FEAT);
}